// round 16
// baseline (speedup 1.0000x reference)
#include <cuda_runtime.h>
#include <cuda_bf16.h>
#include <cuda_fp16.h>
#include <math.h>
#include <stdint.h>

#define NN 50000
#define EE 500000
#define BN_EPS 1e-5f

// ---------------- global scratch ----------------
__device__ __half g_PQ[NN * 256];              // fp16: [n][0:128]=P(dst), [128:256]=Q(src)
__device__ __half g_X2[(size_t)EE * 128];
__device__ __half g_S[(size_t)EE * 128];
__device__ float g_diff[EE * 2];
__device__ float g_dist[EE];
__device__ float g_sp[EE];
__device__ float g_haggr[NN * 128];
__device__ float g_possum[NN * 2];
__device__ int   g_deg[NN];
__device__ float g_U[NN * 128];
__device__ double g_sum[5 * 128];
__device__ double g_sumsq[5 * 128];
// prestaged weights, smem-image layout:
// chunk c (32 k-cols): [plane(2)][n(128)][40], 10240 elems per chunk; cols 32..39 = 0
__device__ __nv_bfloat16 g_wpq[2 * 4 * 10240];   // bf16 hi/lo (node GEMM PQ)
__device__ __nv_bfloat16 g_wu[8 * 10240];        // bf16 hi/lo (update GEMM)
__device__ __half g_wm2[4 * 10240];              // fp16 hi/lo (edge GEMM2)
__device__ __half g_wp1[4 * 10240];              // fp16 hi/lo (edge GEMM3)

// ---------------- helpers ----------------
__device__ __forceinline__ void red_add_v4(float* p, float4 v) {
    asm volatile("red.global.add.v4.f32 [%0], {%1,%2,%3,%4};"
                 :: "l"(p), "f"(v.x), "f"(v.y), "f"(v.z), "f"(v.w) : "memory");
}
__device__ __forceinline__ void red_add_v2(float* p, float2 v) {
    asm volatile("red.global.add.v2.f32 [%0], {%1,%2};"
                 :: "l"(p), "f"(v.x), "f"(v.y) : "memory");
}
__device__ __forceinline__ void red_add_f64(double* p, double v) {
    asm volatile("red.global.add.f64 [%0], %1;" :: "l"(p), "d"(v) : "memory");
}
__device__ __forceinline__ unsigned pkbf(__nv_bfloat16 a, __nv_bfloat16 b) {
    return ((unsigned)__bfloat16_as_ushort(b) << 16) | (unsigned)__bfloat16_as_ushort(a);
}
__device__ __forceinline__ unsigned pkhf(__half a, __half b) {
    return ((unsigned)__half_as_ushort(b) << 16) | (unsigned)__half_as_ushort(a);
}
__device__ __forceinline__ void split1(float x, __nv_bfloat16& h, __nv_bfloat16& l) {
    h = __float2bfloat16(x);
    l = __float2bfloat16(x - __bfloat162float(h));
}
__device__ __forceinline__ void split1h(float x, __half& h, __half& l) {
    h = __float2half_rn(x);
    l = __float2half_rn(x - __half2float(h));
}
__device__ __forceinline__ void mma_bf16(float* d, const unsigned* a, unsigned b0, unsigned b1) {
    asm volatile("mma.sync.aligned.m16n8k16.row.col.f32.bf16.bf16.f32 "
                 "{%0,%1,%2,%3},{%4,%5,%6,%7},{%8,%9},{%0,%1,%2,%3};"
                 : "+f"(d[0]), "+f"(d[1]), "+f"(d[2]), "+f"(d[3])
                 : "r"(a[0]), "r"(a[1]), "r"(a[2]), "r"(a[3]), "r"(b0), "r"(b1));
}
__device__ __forceinline__ void mma_f16(float* d, const unsigned* a, unsigned b0, unsigned b1) {
    asm volatile("mma.sync.aligned.m16n8k16.row.col.f32.f16.f16.f32 "
                 "{%0,%1,%2,%3},{%4,%5,%6,%7},{%8,%9},{%0,%1,%2,%3};"
                 : "+f"(d[0]), "+f"(d[1]), "+f"(d[2]), "+f"(d[3])
                 : "r"(a[0]), "r"(a[1]), "r"(a[2]), "r"(a[3]), "r"(b0), "r"(b1));
}
__device__ __forceinline__ float4 dec4(uint2 r) {
    __half2 a = *(__half2*)&r.x, b = *(__half2*)&r.y;
    return make_float4(__low2float(a), __high2float(a), __low2float(b), __high2float(b));
}
// BN affine from raw stats (bit-identical to former k_fin math)
__device__ __forceinline__ void bn_affine(const double* sum, const double* sumsq,
                                          const float* g, const float* bb,
                                          int c, int rows, float& a, float& cc) {
    double m = sum[c] / rows;
    double v = sumsq[c] / rows - m * m;
    float rstd = rsqrtf((float)v + BN_EPS);
    a = g[c] * rstd;
    cc = bb[c] - (float)m * a;
}

#define W_CHUNK 10240            // elements per W chunk (2 planes x 128 x 40)
#define W_PLANE 5120
#define A_CHUNK1 5120            // fp16 A: 1 plane x 128 x 40
#define A_CHUNK2 10240           // bf16 A: 2 planes x 128 x 40
#define A_PLANE 5120
#define STAGE_F32  (128 * 132)   // 67584 bytes as fp32
#define ETILES 3907              // ceil(EE/128)
#define NTILES 391               // ceil(NN/128)

// persistent EDGE kernel smem: [W 81920][shared: stage 67584 | A 2x10240B][red 4096][bn 1024]
#define PW_BYTES   (4 * W_CHUNK * 2)
#define P_SH_OFF   PW_BYTES
#define P_RED_OFF  (PW_BYTES + STAGE_F32 * 4)
#define P_BN_OFF   (P_RED_OFF + 4096)
#define P_SMEM     (P_BN_OFF + 1024)                   // 154624

// persistent PQ kernel smem: [W 81920][A 2x20480][stage 67584]
#define Q_A_OFF    PW_BYTES
#define Q_ST_OFF   (PW_BYTES + 2 * A_CHUNK2 * 2)
#define Q_SMEM     (Q_ST_OFF + STAGE_F32 * 4)          // 190464

// ---------------- zero scratch ----------------
__global__ void k_zero() {
    int idx = blockIdx.x * blockDim.x + threadIdx.x;
    int stride = gridDim.x * blockDim.x;
    for (int i = idx; i < NN * 128; i += stride) g_haggr[i] = 0.f;
    for (int i = idx; i < NN * 2; i += stride) g_possum[i] = 0.f;
    for (int i = idx; i < NN; i += stride) g_deg[i] = 0;
    if (idx < 5 * 128) { g_sum[idx] = 0.0; g_sumsq[idx] = 0.0; }
}

// ---------------- weight prep ----------------
__global__ void k_prepw(const float* __restrict__ Wm1, const float* __restrict__ Wm2,
                        const float* __restrict__ Wp1, const float* __restrict__ Wu1)
{
    int idx = blockIdx.x * blockDim.x + threadIdx.x;
    int stride = gridDim.x * blockDim.x;
    for (int i = idx; i < 2 * 4 * W_CHUNK; i += stride) {
        int ci = i / W_CHUNK, rem = i % W_CHUNK;
        int plane = rem / W_PLANE, r2 = rem % W_PLANE;
        int n = r2 / 40, k = r2 % 40;
        int nt = ci >> 2, kc = ci & 3, kg = kc * 32 + k;
        float v = 0.f;
        if (k < 32) v = nt ? Wm1[(128 + kg) * 128 + n] : Wm1[kg * 128 + n];
        __nv_bfloat16 h, l; split1(v, h, l);
        g_wpq[i] = plane ? l : h;
    }
    for (int i = idx; i < 4 * W_CHUNK; i += stride) {
        int ci = i / W_CHUNK, rem = i % W_CHUNK;
        int plane = rem / W_PLANE, r2 = rem % W_PLANE;
        int n = r2 / 40, k = r2 % 40;
        int kg = ci * 32 + k;
        float v2 = (k < 32) ? Wm2[kg * 128 + n] : 0.f;
        float vp = (k < 32) ? Wp1[kg * 128 + n] : 0.f;
        __half h, l;
        split1h(v2, h, l); g_wm2[i] = plane ? l : h;
        split1h(vp, h, l); g_wp1[i] = plane ? l : h;
    }
    for (int i = idx; i < 8 * W_CHUNK; i += stride) {
        int ci = i / W_CHUNK, rem = i % W_CHUNK;
        int plane = rem / W_PLANE, r2 = rem % W_PLANE;
        int n = r2 / 40, k = r2 % 40;
        int kg = ci * 32 + k;
        float v = (k < 32) ? Wu1[kg * 128 + n] : 0.f;
        __nv_bfloat16 h, l; split1(v, h, l);
        g_wu[i] = plane ? l : h;
    }
}

// ---------------- persistent PQ GEMM: bf16 3-split, fp16 out, W once ----------------
__global__ __launch_bounds__(512) void k_gemm_pq(
    const float* __restrict__ A, const __nv_bfloat16* __restrict__ Wt,
    __half* __restrict__ PQout)
{
    extern __shared__ char smem[];
    unsigned short* smW = (unsigned short*)smem;
    unsigned short* smA = (unsigned short*)(smem + Q_A_OFF);
    float* stage = (float*)(smem + Q_ST_OFF);

    const int t = threadIdx.x;
    const int w = t >> 5, l = t & 31;
    const int wm = w & 3, wn = w >> 2;
    const int lr = l >> 2, lc = 2 * (l & 3);
    const int ncolBase = blockIdx.y * 128;
    const int rl = t >> 2;
    const int cg = (t & 3) * 8;

    {
        const uint4* s4 = (const uint4*)((const char*)Wt + (size_t)blockIdx.y * 4 * W_CHUNK * 2);
        uint4* d4 = (uint4*)smW;
#pragma unroll 4
        for (int i = t; i < PW_BYTES / 16; i += 512) d4[i] = s4[i];
    }
    __syncthreads();

    for (int tile = blockIdx.x; tile < NTILES; tile += gridDim.x) {
        const int rowBase = tile * 128;
        const int grow = rowBase + rl;
        const bool avalid = grow < NN;

        float acc[2][4][4];
#pragma unroll
        for (int i = 0; i < 2; i++)
#pragma unroll
            for (int j = 0; j < 4; j++)
#pragma unroll
                for (int k = 0; k < 4; k++) acc[i][j][k] = 0.f;

        float4 pv0, pv1;
        auto loadA = [&](int kc) {
            int kg = kc * 32 + cg;
            if (avalid) {
                pv0 = *(const float4*)(A + (size_t)grow * 128 + kg);
                pv1 = *(const float4*)(A + (size_t)grow * 128 + kg + 4);
            }
        };
        auto storeA = [&](int st) {
            float vv[8] = {0.f, 0.f, 0.f, 0.f, 0.f, 0.f, 0.f, 0.f};
            if (avalid) {
                vv[0] = pv0.x; vv[1] = pv0.y; vv[2] = pv0.z; vv[3] = pv0.w;
                vv[4] = pv1.x; vv[5] = pv1.y; vv[6] = pv1.z; vv[7] = pv1.w;
            }
            unsigned ph[4], pl[4];
#pragma unroll
            for (int j = 0; j < 4; j++) {
                __nv_bfloat16 h0, l0, h1, l1;
                split1(vv[2 * j], h0, l0);
                split1(vv[2 * j + 1], h1, l1);
                ph[j] = pkbf(h0, h1);
                pl[j] = pkbf(l0, l1);
            }
            unsigned short* Ah = smA + st * A_CHUNK2;
            *(uint4*)(Ah + rl * 40 + cg) = make_uint4(ph[0], ph[1], ph[2], ph[3]);
            *(uint4*)(Ah + A_PLANE + rl * 40 + cg) = make_uint4(pl[0], pl[1], pl[2], pl[3]);
        };

        loadA(0);
        storeA(0);
        __syncthreads();

        for (int kc = 0; kc < 4; kc++) {
            if (kc + 1 < 4) loadA(kc + 1);
            const unsigned short* Ah = smA + (kc & 1) * A_CHUNK2;
            const unsigned short* Al = Ah + A_PLANE;
            const unsigned short* Bh = smW + kc * W_CHUNK;
            const unsigned short* Bl = Bh + W_PLANE;
#pragma unroll
            for (int ks = 0; ks < 2; ks++) {
                int kb = ks * 16;
                unsigned ah[2][4], al2[2][4];
#pragma unroll
                for (int mt = 0; mt < 2; mt++) {
                    int rb = wm * 32 + mt * 16 + lr;
                    ah[mt][0] = *(const unsigned*)(Ah + rb * 40 + kb + lc);
                    ah[mt][1] = *(const unsigned*)(Ah + (rb + 8) * 40 + kb + lc);
                    ah[mt][2] = *(const unsigned*)(Ah + rb * 40 + kb + lc + 8);
                    ah[mt][3] = *(const unsigned*)(Ah + (rb + 8) * 40 + kb + lc + 8);
                    al2[mt][0] = *(const unsigned*)(Al + rb * 40 + kb + lc);
                    al2[mt][1] = *(const unsigned*)(Al + (rb + 8) * 40 + kb + lc);
                    al2[mt][2] = *(const unsigned*)(Al + rb * 40 + kb + lc + 8);
                    al2[mt][3] = *(const unsigned*)(Al + (rb + 8) * 40 + kb + lc + 8);
                }
#pragma unroll
                for (int nt = 0; nt < 4; nt++) {
                    int nb = wn * 32 + nt * 8 + lr;
                    unsigned bh0 = *(const unsigned*)(Bh + nb * 40 + kb + lc);
                    unsigned bh1 = *(const unsigned*)(Bh + nb * 40 + kb + lc + 8);
                    unsigned bl0 = *(const unsigned*)(Bl + nb * 40 + kb + lc);
                    unsigned bl1 = *(const unsigned*)(Bl + nb * 40 + kb + lc + 8);
#pragma unroll
                    for (int mt = 0; mt < 2; mt++) {
                        mma_bf16(acc[mt][nt], ah[mt], bh0, bh1);
                        mma_bf16(acc[mt][nt], ah[mt], bl0, bl1);
                        mma_bf16(acc[mt][nt], al2[mt], bh0, bh1);
                    }
                }
            }
            if (kc + 1 < 4) {
                storeA((kc + 1) & 1);
                __syncthreads();
            }
        }

#pragma unroll
        for (int mt = 0; mt < 2; mt++) {
#pragma unroll
            for (int nt = 0; nt < 4; nt++) {
                int row = wm * 32 + mt * 16 + lr;
                int col = wn * 32 + nt * 8 + lc;
                stage[row * 132 + col]           = acc[mt][nt][0];
                stage[row * 132 + col + 1]       = acc[mt][nt][1];
                stage[(row + 8) * 132 + col]     = acc[mt][nt][2];
                stage[(row + 8) * 132 + col + 1] = acc[mt][nt][3];
            }
        }
        __syncthreads();

        for (int i = t; i < 128 * 32; i += 512) {
            int row = i >> 5;
            int colq = (i & 31) * 4;
            int rowg = rowBase + row;
            if (rowg < NN) {
                float4 v = *(float4*)(stage + row * 132 + colq);
                uint2 o = make_uint2(pkhf(__float2half_rn(v.x), __float2half_rn(v.y)),
                                     pkhf(__float2half_rn(v.z), __float2half_rn(v.w)));
                *(uint2*)(PQout + (size_t)rowg * 256 + ncolBase + colq) = o;
            }
        }
        __syncthreads();
    }
}

// ---------------- node GEMM (update MLP): bf16 3-split, fp32 out ----------------
__global__ __launch_bounds__(512) void k_gemm_u(
    const float* __restrict__ A, const float* __restrict__ A2,
    const __nv_bfloat16* __restrict__ Wt, const float* __restrict__ bias,
    float* __restrict__ Cf,
    double* __restrict__ sumOut, double* __restrict__ sumsqOut)
{
    extern __shared__ char smem[];
    unsigned short* smW = (unsigned short*)smem;
    unsigned short* smA = smW + 8 * W_CHUNK;

    const int t = threadIdx.x;
    const int w = t >> 5, l = t & 31;
    const int wm = w & 3, wn = w >> 2;
    const int lr = l >> 2, lc = 2 * (l & 3);
    const int rowBase = blockIdx.x * 128;

    {
        const uint4* s4 = (const uint4*)Wt;
        uint4* d4 = (uint4*)smW;
        const int tot = 8 * W_CHUNK * 2 / 16;
#pragma unroll 4
        for (int i = t; i < tot; i += 512) d4[i] = s4[i];
    }

    const int rl = t >> 2;
    const int cg = (t & 3) * 8;
    const int grow = rowBase + rl;
    const bool avalid = grow < NN;

    float acc[2][4][4];
#pragma unroll
    for (int i = 0; i < 2; i++)
#pragma unroll
        for (int j = 0; j < 4; j++)
#pragma unroll
            for (int k = 0; k < 4; k++) acc[i][j][k] = 0.f;

    float4 pv0, pv1;
    auto loadA = [&](int kc) {
        int kg = kc * 32 + cg;
        if (avalid) {
            const float* As = (kg < 128) ? A : A2;
            int k2 = kg & 127;
            pv0 = *(const float4*)(As + (size_t)grow * 128 + k2);
            pv1 = *(const float4*)(As + (size_t)grow * 128 + k2 + 4);
        }
    };
    auto storeA = [&](int st) {
        float vv[8] = {0.f, 0.f, 0.f, 0.f, 0.f, 0.f, 0.f, 0.f};
        if (avalid) {
            vv[0] = pv0.x; vv[1] = pv0.y; vv[2] = pv0.z; vv[3] = pv0.w;
            vv[4] = pv1.x; vv[5] = pv1.y; vv[6] = pv1.z; vv[7] = pv1.w;
        }
        unsigned ph[4], pl[4];
#pragma unroll
        for (int j = 0; j < 4; j++) {
            __nv_bfloat16 h0, l0, h1, l1;
            split1(vv[2 * j], h0, l0);
            split1(vv[2 * j + 1], h1, l1);
            ph[j] = pkbf(h0, h1);
            pl[j] = pkbf(l0, l1);
        }
        unsigned short* Ah = smA + st * A_CHUNK2;
        *(uint4*)(Ah + rl * 40 + cg) = make_uint4(ph[0], ph[1], ph[2], ph[3]);
        *(uint4*)(Ah + A_PLANE + rl * 40 + cg) = make_uint4(pl[0], pl[1], pl[2], pl[3]);
    };

    loadA(0);
    storeA(0);
    __syncthreads();

    for (int kc = 0; kc < 8; kc++) {
        if (kc + 1 < 8) loadA(kc + 1);
        const unsigned short* Ah = smA + (kc & 1) * A_CHUNK2;
        const unsigned short* Al = Ah + A_PLANE;
        const unsigned short* Bh = smW + kc * W_CHUNK;
        const unsigned short* Bl = Bh + W_PLANE;
#pragma unroll
        for (int ks = 0; ks < 2; ks++) {
            int kb = ks * 16;
            unsigned ah[2][4], al2[2][4];
#pragma unroll
            for (int mt = 0; mt < 2; mt++) {
                int rb = wm * 32 + mt * 16 + lr;
                ah[mt][0] = *(const unsigned*)(Ah + rb * 40 + kb + lc);
                ah[mt][1] = *(const unsigned*)(Ah + (rb + 8) * 40 + kb + lc);
                ah[mt][2] = *(const unsigned*)(Ah + rb * 40 + kb + lc + 8);
                ah[mt][3] = *(const unsigned*)(Ah + (rb + 8) * 40 + kb + lc + 8);
                al2[mt][0] = *(const unsigned*)(Al + rb * 40 + kb + lc);
                al2[mt][1] = *(const unsigned*)(Al + (rb + 8) * 40 + kb + lc);
                al2[mt][2] = *(const unsigned*)(Al + rb * 40 + kb + lc + 8);
                al2[mt][3] = *(const unsigned*)(Al + (rb + 8) * 40 + kb + lc + 8);
            }
#pragma unroll
            for (int nt = 0; nt < 4; nt++) {
                int nb = wn * 32 + nt * 8 + lr;
                unsigned bh0 = *(const unsigned*)(Bh + nb * 40 + kb + lc);
                unsigned bh1 = *(const unsigned*)(Bh + nb * 40 + kb + lc + 8);
                unsigned bl0 = *(const unsigned*)(Bl + nb * 40 + kb + lc);
                unsigned bl1 = *(const unsigned*)(Bl + nb * 40 + kb + lc + 8);
#pragma unroll
                for (int mt = 0; mt < 2; mt++) {
                    mma_bf16(acc[mt][nt], ah[mt], bh0, bh1);
                    mma_bf16(acc[mt][nt], ah[mt], bl0, bl1);
                    mma_bf16(acc[mt][nt], al2[mt], bh0, bh1);
                }
            }
        }
        if (kc + 1 < 8) {
            storeA((kc + 1) & 1);
            __syncthreads();
        }
    }
    __syncthreads();

    float* stage = (float*)smem;
#pragma unroll
    for (int mt = 0; mt < 2; mt++) {
#pragma unroll
        for (int nt = 0; nt < 4; nt++) {
            int row = wm * 32 + mt * 16 + lr;
            int col = wn * 32 + nt * 8 + lc;
            float b0 = __ldg(bias + col);
            float b1 = __ldg(bias + col + 1);
            bool v0 = (rowBase + row) < NN;
            bool v1 = (rowBase + row + 8) < NN;
            stage[row * 132 + col]       = v0 ? acc[mt][nt][0] + b0 : 0.f;
            stage[row * 132 + col + 1]   = v0 ? acc[mt][nt][1] + b1 : 0.f;
            stage[(row + 8) * 132 + col]     = v1 ? acc[mt][nt][2] + b0 : 0.f;
            stage[(row + 8) * 132 + col + 1] = v1 ? acc[mt][nt][3] + b1 : 0.f;
        }
    }
    __syncthreads();

    float* sb = (float*)(smem + STAGE_F32 * 4);
    float* qb = sb + 512;
    {
        int c = t & 127, qq = t >> 7;
        float s = 0.f, q = 0.f;
#pragma unroll 8
        for (int r = 0; r < 32; r++) {
            float v = stage[(qq * 32 + r) * 132 + c];
            s += v; q += v * v;
        }
        sb[qq * 128 + c] = s;
        qb[qq * 128 + c] = q;
    }

    for (int i = t; i < 128 * 32; i += 512) {
        int row = i >> 5;
        int colq = (i & 31) * 4;
        int rowg = rowBase + row;
        if (rowg < NN) {
            float4 v = *(float4*)(stage + row * 132 + colq);
            *(float4*)(Cf + (size_t)rowg * 128 + colq) = v;
        }
    }

    __syncthreads();
    if (t < 128) {
        float s = sb[t] + sb[128 + t] + sb[256 + t] + sb[384 + t];
        float q = qb[t] + qb[128 + t] + qb[256 + t] + qb[384 + t];
        red_add_f64(&sumOut[t], (double)s);
        red_add_f64(&sumsqOut[t], (double)q);
    }
}

// ---------------- persistent edge GEMM: fp16, W once, inline BN-affine preamble ----------------
// AMODE 2: assemble from fp16 g_PQ (GEMM2);  AMODE 3: fp16 A rows (GEMM3)
template<int AMODE, bool AGGR>
__global__ __launch_bounds__(512) void k_gemm_p(
    const __half* __restrict__ Ain,
    const __half* __restrict__ Wt,
    const float* __restrict__ bias,
    const double* __restrict__ sumIn, const double* __restrict__ sumsqIn,
    const float* __restrict__ gammaIn, const float* __restrict__ betaIn,
    __half* __restrict__ Ch,
    const int* __restrict__ srcIdx, const int* __restrict__ dstIdx,
    const float* __restrict__ dist,
    const float* __restrict__ wlast, const float* __restrict__ bm1v,
    double* __restrict__ sumOut, double* __restrict__ sumsqOut,
    float* __restrict__ aggrOut)
{
    extern __shared__ char smem[];
    unsigned short* smW = (unsigned short*)smem;
    unsigned short* smA = (unsigned short*)(smem + P_SH_OFF);
    float* stage = (float*)(smem + P_SH_OFF);
    float* sb = (float*)(smem + P_RED_OFF);
    float* qb = sb + 512;
    float* bna = (float*)(smem + P_BN_OFF);
    float* bnc = bna + 128;

    const int t = threadIdx.x;
    const int w = t >> 5, l = t & 31;
    const int wm = w & 3, wn = w >> 2;
    const int lr = l >> 2, lc = 2 * (l & 3);
    const int rl = t >> 2;
    const int cg = (t & 3) * 8;

    // inline BN affine (replaces k_fin launch)
    if (t < 128) {
        float a, c;
        bn_affine(sumIn, sumsqIn, gammaIn, betaIn, t, EE, a, c);
        bna[t] = a;
        bnc[t] = c;
    }
    {
        const uint4* s4 = (const uint4*)Wt;
        uint4* d4 = (uint4*)smW;
#pragma unroll 4
        for (int i = t; i < PW_BYTES / 16; i += 512) d4[i] = s4[i];
    }
    __syncthreads();

    for (int tile = blockIdx.x; tile < ETILES; tile += gridDim.x) {
        const int rowBase = tile * 128;
        const int grow = rowBase + rl;
        const bool avalid = grow < EE;
        int ed = 0, es = 0;
        float de = 0.f;
        if (avalid) {
            if (AMODE == 2 || AGGR) ed = dstIdx[grow];
            if (AMODE == 2) { es = srcIdx[grow]; de = dist[grow]; }
        }

        float acc[2][4][4];
#pragma unroll
        for (int i = 0; i < 2; i++)
#pragma unroll
            for (int j = 0; j < 4; j++)
#pragma unroll
                for (int k = 0; k < 4; k++) acc[i][j][k] = 0.f;

        float4 pv0, pv1, pv2, pv3;

        auto loadA = [&](int kc) {
            int kg = kc * 32 + cg;
            if (avalid) {
                if (AMODE == 3) {
                    uint4 r = *(const uint4*)(Ain + (size_t)grow * 128 + kg);
                    pv0 = dec4(make_uint2(r.x, r.y));
                    pv1 = dec4(make_uint2(r.z, r.w));
                } else {
                    uint4 rp = *(const uint4*)(g_PQ + (size_t)ed * 256 + kg);
                    uint4 rq = *(const uint4*)(g_PQ + (size_t)es * 256 + 128 + kg);
                    pv0 = dec4(make_uint2(rp.x, rp.y));
                    pv1 = dec4(make_uint2(rp.z, rp.w));
                    pv2 = dec4(make_uint2(rq.x, rq.y));
                    pv3 = dec4(make_uint2(rq.z, rq.w));
                }
            }
        };
        auto storeA = [&](int kc, int st) {
            int kg = kc * 32 + cg;
            float vv[8] = {0.f, 0.f, 0.f, 0.f, 0.f, 0.f, 0.f, 0.f};
            if (avalid) {
                vv[0] = pv0.x; vv[1] = pv0.y; vv[2] = pv0.z; vv[3] = pv0.w;
                vv[4] = pv1.x; vv[5] = pv1.y; vv[6] = pv1.z; vv[7] = pv1.w;
                if (AMODE == 2) {
                    float q4[8] = {pv2.x, pv2.y, pv2.z, pv2.w, pv3.x, pv3.y, pv3.z, pv3.w};
#pragma unroll
                    for (int j = 0; j < 8; j++) {
                        float wl = __ldg(wlast + kg + j);
                        float bb = __ldg(bm1v + kg + j);
                        vv[j] = vv[j] + q4[j] + de * wl + bb;
                    }
                }
                float4 a0 = *(const float4*)(bna + kg);
                float4 a1 = *(const float4*)(bna + kg + 4);
                float4 c0 = *(const float4*)(bnc + kg);
                float4 c1 = *(const float4*)(bnc + kg + 4);
                vv[0] = fmaxf(fmaf(vv[0], a0.x, c0.x), 0.f);
                vv[1] = fmaxf(fmaf(vv[1], a0.y, c0.y), 0.f);
                vv[2] = fmaxf(fmaf(vv[2], a0.z, c0.z), 0.f);
                vv[3] = fmaxf(fmaf(vv[3], a0.w, c0.w), 0.f);
                vv[4] = fmaxf(fmaf(vv[4], a1.x, c1.x), 0.f);
                vv[5] = fmaxf(fmaf(vv[5], a1.y, c1.y), 0.f);
                vv[6] = fmaxf(fmaf(vv[6], a1.z, c1.z), 0.f);
                vv[7] = fmaxf(fmaf(vv[7], a1.w, c1.w), 0.f);
                if (AGGR) {
                    red_add_v4(aggrOut + (size_t)ed * 128 + kg,
                               make_float4(vv[0], vv[1], vv[2], vv[3]));
                    red_add_v4(aggrOut + (size_t)ed * 128 + kg + 4,
                               make_float4(vv[4], vv[5], vv[6], vv[7]));
                }
            }
            unsigned ph[4];
#pragma unroll
            for (int j = 0; j < 4; j++)
                ph[j] = pkhf(__float2half_rn(vv[2 * j]), __float2half_rn(vv[2 * j + 1]));
            unsigned short* Ah = smA + st * A_CHUNK1;
            *(uint4*)(Ah + rl * 40 + cg) = make_uint4(ph[0], ph[1], ph[2], ph[3]);
        };

        loadA(0);
        storeA(0, 0);
        __syncthreads();

        for (int kc = 0; kc < 4; kc++) {
            if (kc + 1 < 4) loadA(kc + 1);
            const unsigned short* Ah = smA + (kc & 1) * A_CHUNK1;
            const unsigned short* Bh = smW + kc * W_CHUNK;
            const unsigned short* Bl = Bh + W_PLANE;
#pragma unroll
            for (int ks = 0; ks < 2; ks++) {
                int kb = ks * 16;
                unsigned ah[2][4];
#pragma unroll
                for (int mt = 0; mt < 2; mt++) {
                    int rb = wm * 32 + mt * 16 + lr;
                    ah[mt][0] = *(const unsigned*)(Ah + rb * 40 + kb + lc);
                    ah[mt][1] = *(const unsigned*)(Ah + (rb + 8) * 40 + kb + lc);
                    ah[mt][2] = *(const unsigned*)(Ah + rb * 40 + kb + lc + 8);
                    ah[mt][3] = *(const unsigned*)(Ah + (rb + 8) * 40 + kb + lc + 8);
                }
#pragma unroll
                for (int nt = 0; nt < 4; nt++) {
                    int nb = wn * 32 + nt * 8 + lr;
                    unsigned bh0 = *(const unsigned*)(Bh + nb * 40 + kb + lc);
                    unsigned bh1 = *(const unsigned*)(Bh + nb * 40 + kb + lc + 8);
                    unsigned bl0 = *(const unsigned*)(Bl + nb * 40 + kb + lc);
                    unsigned bl1 = *(const unsigned*)(Bl + nb * 40 + kb + lc + 8);
#pragma unroll
                    for (int mt = 0; mt < 2; mt++) {
                        mma_f16(acc[mt][nt], ah[mt], bh0, bh1);
                        mma_f16(acc[mt][nt], ah[mt], bl0, bl1);
                    }
                }
            }
            if (kc + 1 < 4) {
                storeA(kc + 1, (kc + 1) & 1);
                __syncthreads();
            }
        }
        __syncthreads();   // A-buffer reads done; stage may overwrite region

#pragma unroll
        for (int mt = 0; mt < 2; mt++) {
#pragma unroll
            for (int nt = 0; nt < 4; nt++) {
                int row = wm * 32 + mt * 16 + lr;
                int col = wn * 32 + nt * 8 + lc;
                float b0 = __ldg(bias + col);
                float b1 = __ldg(bias + col + 1);
                bool v0 = (rowBase + row) < EE;
                bool v1 = (rowBase + row + 8) < EE;
                stage[row * 132 + col]       = v0 ? acc[mt][nt][0] + b0 : 0.f;
                stage[row * 132 + col + 1]   = v0 ? acc[mt][nt][1] + b1 : 0.f;
                stage[(row + 8) * 132 + col]     = v1 ? acc[mt][nt][2] + b0 : 0.f;
                stage[(row + 8) * 132 + col + 1] = v1 ? acc[mt][nt][3] + b1 : 0.f;
            }
        }
        __syncthreads();

        {
            int c = t & 127, qq = t >> 7;
            float s = 0.f, q = 0.f;
#pragma unroll 8
            for (int r = 0; r < 32; r++) {
                float v = stage[(qq * 32 + r) * 132 + c];
                s += v; q += v * v;
            }
            sb[qq * 128 + c] = s;
            qb[qq * 128 + c] = q;
        }

        for (int i = t; i < 128 * 32; i += 512) {
            int row = i >> 5;
            int colq = (i & 31) * 4;
            int rowg = rowBase + row;
            if (rowg < EE) {
                float4 v = *(float4*)(stage + row * 132 + colq);
                uint2 o = make_uint2(pkhf(__float2half_rn(v.x), __float2half_rn(v.y)),
                                     pkhf(__float2half_rn(v.z), __float2half_rn(v.w)));
                *(uint2*)(Ch + (size_t)rowg * 128 + colq) = o;
            }
        }
        __syncthreads();   // stage reads done before next tile's storeA

        if (t < 128) {
            float s = sb[t] + sb[128 + t] + sb[256 + t] + sb[384 + t];
            float q = qb[t] + qb[128 + t] + qb[256 + t] + qb[384 + t];
            red_add_f64(&sumOut[t], (double)s);
            red_add_f64(&sumsqOut[t], (double)q);
        }
    }
}

// ---------------- edge stats (BN1), fp16 PQ, 2-way unrolled + deg histogram ----------------
__global__ __launch_bounds__(256) void k_edgestats(
    const int* __restrict__ src, const int* __restrict__ dst,
    const float* __restrict__ pos,
    const float* __restrict__ wlast, const float* __restrict__ bm1,
    double* __restrict__ sum, double* __restrict__ sumsq)
{
    int lane = threadIdx.x & 31;
    int wg = (blockIdx.x * blockDim.x + threadIdx.x) >> 5;
    int nw = (gridDim.x * blockDim.x) >> 5;
    int c = lane * 4;
    float4 wl = *(const float4*)(wlast + c);
    float4 bb = *(const float4*)(bm1 + c);
    float4 s = make_float4(0.f, 0.f, 0.f, 0.f);
    float4 q = make_float4(0.f, 0.f, 0.f, 0.f);
    int nw2 = nw * 2;
    for (int e = wg; e < EE; e += nw2) {
        int eB = e + nw;
        bool hasB = eB < EE;
        int sjA = src[e], djA = dst[e];
        int sjB = hasB ? src[eB] : 0, djB = hasB ? dst[eB] : 0;
        float2 psA = ((const float2*)pos)[sjA];
        float2 pdA = ((const float2*)pos)[djA];
        float2 psB = ((const float2*)pos)[sjB];
        float2 pdB = ((const float2*)pos)[djB];
        float4 pA = dec4(*(const uint2*)(g_PQ + (size_t)djA * 256 + c));
        float4 qA = dec4(*(const uint2*)(g_PQ + (size_t)sjA * 256 + 128 + c));
        float4 pB = dec4(*(const uint2*)(g_PQ + (size_t)djB * 256 + c));
        float4 qB = dec4(*(const uint2*)(g_PQ + (size_t)sjB * 256 + 128 + c));

        float dxA = psA.x - pdA.x, dyA = psA.y - pdA.y;
        float dA = sqrtf(dxA * dxA + dyA * dyA);
        float dxB = psB.x - pdB.x, dyB = psB.y - pdB.y;
        float dB = sqrtf(dxB * dxB + dyB * dyB);
        if (lane == 0) {
            ((float2*)g_diff)[e] = make_float2(dxA, dyA);
            g_dist[e] = dA;
            atomicAdd(&g_deg[djA], 1);
            if (hasB) {
                ((float2*)g_diff)[eB] = make_float2(dxB, dyB);
                g_dist[eB] = dB;
                atomicAdd(&g_deg[djB], 1);
            }
        }
        float4 x;
        x.x = pA.x + qA.x + dA * wl.x + bb.x;
        x.y = pA.y + qA.y + dA * wl.y + bb.y;
        x.z = pA.z + qA.z + dA * wl.z + bb.z;
        x.w = pA.w + qA.w + dA * wl.w + bb.w;
        s.x += x.x; s.y += x.y; s.z += x.z; s.w += x.w;
        q.x += x.x * x.x; q.y += x.y * x.y; q.z += x.z * x.z; q.w += x.w * x.w;
        if (hasB) {
            float4 y;
            y.x = pB.x + qB.x + dB * wl.x + bb.x;
            y.y = pB.y + qB.y + dB * wl.y + bb.y;
            y.z = pB.z + qB.z + dB * wl.z + bb.z;
            y.w = pB.w + qB.w + dB * wl.w + bb.w;
            s.x += y.x; s.y += y.y; s.z += y.z; s.w += y.w;
            q.x += y.x * y.x; q.y += y.y * y.y; q.z += y.z * y.z; q.w += y.w * y.w;
        }
    }
    __shared__ float sb[8][128], qb[8][128];
    int wi = threadIdx.x >> 5;
    *(float4*)&sb[wi][c] = s;
    *(float4*)&qb[wi][c] = q;
    __syncthreads();
    if (threadIdx.x < 128) {
        float ts = 0.f, tq = 0.f;
#pragma unroll
        for (int i = 0; i < 8; i++) { ts += sb[i][threadIdx.x]; tq += qb[i][threadIdx.x]; }
        red_add_f64(&sum[threadIdx.x], (double)ts);
        red_add_f64(&sumsq[threadIdx.x], (double)tq);
    }
}

// ---------------- gemv over fp16 S, inline BN3 affine + fused BN4 stats ----------------
__global__ void k_gemv(const __half* __restrict__ S, const float* __restrict__ Wp2,
                       const float* __restrict__ bp2,
                       const double* __restrict__ sumIn, const double* __restrict__ sumsqIn,
                       const float* __restrict__ gammaIn, const float* __restrict__ betaIn,
                       float* __restrict__ out,
                       double* __restrict__ sum, double* __restrict__ sumsq)
{
    int e = (blockIdx.x * blockDim.x + threadIdx.x) >> 5;
    int lane = threadIdx.x & 31;
    int wi = threadIdx.x >> 5;
    __shared__ float ssb[8], qqb[8];
    __shared__ float bna[128], bnc[128];
    if (threadIdx.x < 128) {
        float a, c;
        bn_affine(sumIn, sumsqIn, gammaIn, betaIn, threadIdx.x, EE, a, c);
        bna[threadIdx.x] = a;
        bnc[threadIdx.x] = c;
    }
    __syncthreads();
    float myval = 0.f;
    if (e < EE) {
        int c = lane * 4;
        float4 v = dec4(*(const uint2*)(S + (size_t)e * 128 + c));
        float4 wv = *(const float4*)(Wp2 + c);
        float4 a = *(const float4*)(bna + c);
        float4 cc = *(const float4*)(bnc + c);
        float d = fmaxf(fmaf(v.x, a.x, cc.x), 0.f) * wv.x
                + fmaxf(fmaf(v.y, a.y, cc.y), 0.f) * wv.y
                + fmaxf(fmaf(v.z, a.z, cc.z), 0.f) * wv.z
                + fmaxf(fmaf(v.w, a.w, cc.w), 0.f) * wv.w;
#pragma unroll
        for (int o = 16; o > 0; o >>= 1) d += __shfl_down_sync(0xffffffffu, d, o);
        if (lane == 0) {
            myval = d + bp2[0];
            out[e] = myval;
        }
    }
    if (lane == 0) { ssb[wi] = myval; qqb[wi] = myval * myval; }
    __syncthreads();
    if (threadIdx.x == 0) {
        float s = 0.f, q = 0.f;
#pragma unroll
        for (int i = 0; i < 8; i++) { s += ssb[i]; q += qqb[i]; }
        red_add_f64(sum, (double)s);
        red_add_f64(sumsq, (double)q);
    }
}

// ---------------- pos aggregation, inline scalar BN4 affine ----------------
__global__ void k_posaggr(const int* __restrict__ dst,
                          const double* __restrict__ sumIn, const double* __restrict__ sumsqIn,
                          const float* __restrict__ gammaIn, const float* __restrict__ betaIn)
{
    int e = blockIdx.x * blockDim.x + threadIdx.x;
    if (e >= EE) return;
    float a4, c4;
    bn_affine(sumIn, sumsqIn, gammaIn, betaIn, 0, EE, a4, c4);
    float sc = fmaxf(fmaf(g_sp[e], a4, c4), 0.f);
    float2 df = ((const float2*)g_diff)[e];
    int d = dst[e];
    red_add_v2(g_possum + 2 * (size_t)d, make_float2(df.x * sc, df.y * sc));
}

// ---------------- final residual write, inline BN5 affine ----------------
__global__ void k_final(const float* __restrict__ h, const float* __restrict__ pos,
                        const double* __restrict__ sumIn, const double* __restrict__ sumsqIn,
                        const float* __restrict__ gammaIn, const float* __restrict__ betaIn,
                        float* __restrict__ out)
{
    __shared__ float bna[128], bnc[128];
    if (threadIdx.x < 128) {
        float a, c;
        bn_affine(sumIn, sumsqIn, gammaIn, betaIn, threadIdx.x, NN, a, c);
        bna[threadIdx.x] = a;
        bnc[threadIdx.x] = c;
    }
    __syncthreads();
    int i = blockIdx.x * blockDim.x + threadIdx.x;
    if (i < NN * 128) {
        int c = i & 127;
        float u = g_U[i];
        out[i] = h[i] + fmaxf(fmaf(u, bna[c], bnc[c]), 0.f);
    }
    if (i < NN) {
        float cnt = fmaxf((float)g_deg[i], 1.f);
        out[NN * 128 + 2 * i + 0] = pos[2 * i + 0] + g_possum[2 * i + 0] / cnt;
        out[NN * 128 + 2 * i + 1] = pos[2 * i + 1] + g_possum[2 * i + 1] / cnt;
    }
}

extern "C" void kernel_launch(void* const* d_in, const int* in_sizes, int n_in,
                              void* d_out, int out_size)
{
    const float* h    = (const float*)d_in[0];
    const float* pos  = (const float*)d_in[1];
    const int*   ei   = (const int*)d_in[3];
    const int*   src  = ei;
    const int*   dst  = ei + EE;
    const float* Wm1  = (const float*)d_in[4];
    const float* bm1  = (const float*)d_in[5];
    const float* gm1  = (const float*)d_in[6];
    const float* bbm1 = (const float*)d_in[7];
    const float* Wm2  = (const float*)d_in[8];
    const float* bm2  = (const float*)d_in[9];
    const float* gm2  = (const float*)d_in[10];
    const float* bbm2 = (const float*)d_in[11];
    const float* Wp1  = (const float*)d_in[12];
    const float* bp1  = (const float*)d_in[13];
    const float* gp1  = (const float*)d_in[14];
    const float* bbp1 = (const float*)d_in[15];
    const float* Wp2  = (const float*)d_in[16];
    const float* bp2  = (const float*)d_in[17];
    const float* gp2  = (const float*)d_in[18];
    const float* bbp2 = (const float*)d_in[19];
    const float* Wu1  = (const float*)d_in[20];
    const float* bu1  = (const float*)d_in[21];
    const float* gu1  = (const float*)d_in[22];
    const float* bbu1 = (const float*)d_in[23];
    float* out = (float*)d_out;

    void* p;
    cudaGetSymbolAddress(&p, g_PQ);   __half* PQ  = (__half*)p;
    cudaGetSymbolAddress(&p, g_X2);   __half* X2  = (__half*)p;
    cudaGetSymbolAddress(&p, g_S);    __half* S   = (__half*)p;
    cudaGetSymbolAddress(&p, g_dist); float* DIST = (float*)p;
    cudaGetSymbolAddress(&p, g_sp);   float* SP   = (float*)p;
    cudaGetSymbolAddress(&p, g_haggr); float* HAGG = (float*)p;
    cudaGetSymbolAddress(&p, g_U);    float* U    = (float*)p;
    cudaGetSymbolAddress(&p, g_sum);  double* SUM = (double*)p;
    cudaGetSymbolAddress(&p, g_sumsq); double* SSQ = (double*)p;
    cudaGetSymbolAddress(&p, g_wpq);  __nv_bfloat16* WPQ = (__nv_bfloat16*)p;
    cudaGetSymbolAddress(&p, g_wm2);  __half* WM2 = (__half*)p;
    cudaGetSymbolAddress(&p, g_wp1);  __half* WP1 = (__half*)p;
    cudaGetSymbolAddress(&p, g_wu);   __nv_bfloat16* WU  = (__nv_bfloat16*)p;

    int nsm = 148;
    cudaDeviceGetAttribute(&nsm, cudaDevAttrMultiProcessorCount, 0);

    const float* wlast = Wm1 + 256 * 128;
    const int SM8B = 8 * 20480 + 2 * 20480;  // 204800 (update GEMM)

    cudaFuncSetAttribute((const void*)k_gemm_pq,
                         cudaFuncAttributeMaxDynamicSharedMemorySize, Q_SMEM);
    cudaFuncSetAttribute((const void*)k_gemm_u,
                         cudaFuncAttributeMaxDynamicSharedMemorySize, SM8B);
    cudaFuncSetAttribute((const void*)k_gemm_p<2, false>,
                         cudaFuncAttributeMaxDynamicSharedMemorySize, P_SMEM);
    cudaFuncSetAttribute((const void*)k_gemm_p<3, true>,
                         cudaFuncAttributeMaxDynamicSharedMemorySize, P_SMEM);

    k_zero<<<2048, 256>>>();
    k_prepw<<<256, 256>>>(Wm1, Wm2, Wp1, Wu1);

    // PQ(fp16) = h @ [Wm1_top | Wm1_mid]  (persistent, bf16 3-split)
    k_gemm_pq<<<dim3(nsm, 2), 512, Q_SMEM>>>(h, WPQ, PQ);

    // BN1 stats + diff/dist/deg (fp16 PQ gather)
    k_edgestats<<<1184, 256>>>(src, dst, pos, wlast, bm1, SUM + 0, SSQ + 0);

    // GEMM2 (persistent): inline BN1 affine; X2(fp16) = bn_relu1(assemble) @ Wm2 + bm2
    k_gemm_p<2, false><<<nsm, 512, P_SMEM>>>(
        nullptr, WM2, bm2, SUM + 0, SSQ + 0, gm1, bbm1, X2,
        src, dst, DIST, wlast, bm1, SUM + 128, SSQ + 128, nullptr);

    // GEMM3 (persistent): inline BN2 affine; S(fp16) = bn_relu2(X2) @ Wp1 + bp1 + h-aggr
    k_gemm_p<3, true><<<nsm, 512, P_SMEM>>>(
        X2, WP1, bp1, SUM + 128, SSQ + 128, gm2, bbm2, S,
        nullptr, dst, nullptr, nullptr, nullptr, SUM + 256, SSQ + 256, HAGG);

    // pos layer 2: inline BN3 affine + fused BN4 stats
    k_gemv<<<EE / 8, 256>>>(S, Wp2, bp2, SUM + 256, SSQ + 256, gp1, bbp1, SP,
                            SUM + 384, SSQ + 384);

    // pos aggregation: inline scalar BN4 affine
    k_posaggr<<<(EE + 255) / 256, 256>>>(dst, SUM + 384, SSQ + 384, gp2, bbp2);

    // update MLP (bf16 3-split, fused BN5 stats)
    k_gemm_u<<<NTILES, 512, SM8B>>>(h, HAGG, WU, bu1, U, SUM + 512, SSQ + 512);

    // residual outputs: inline BN5 affine
    k_final<<<(NN * 128 + 255) / 256, 256>>>(h, pos, SUM + 512, SSQ + 512, gu1, bbu1, out);
}

// round 17
// speedup vs baseline: 1.3958x; 1.3958x over previous
#include <cuda_runtime.h>
#include <cuda_bf16.h>
#include <cuda_fp16.h>
#include <math.h>
#include <stdint.h>

#define NN 50000
#define EE 500000
#define BN_EPS 1e-5f

// ---------------- global scratch ----------------
__device__ __half g_PQ[NN * 256];              // fp16: [n][0:128]=P(dst), [128:256]=Q(src)
__device__ __half g_X2[(size_t)EE * 128];
__device__ __half g_S[(size_t)EE * 128];
__device__ float g_diff[EE * 2];
__device__ float g_dist[EE];
__device__ float g_sp[EE];
__device__ float g_haggr[NN * 128];
__device__ float g_possum[NN * 2];
__device__ int   g_deg[NN];
__device__ float g_U[NN * 128];
__device__ double g_sum[5 * 128];
__device__ double g_sumsq[5 * 128];
__device__ float g_acta[5 * 128];
__device__ float g_actc[5 * 128];
// prestaged weights, smem-image layout:
// chunk c (32 k-cols): [plane(2)][n(128)][40], 10240 elems per chunk; cols 32..39 = 0
__device__ __nv_bfloat16 g_wpq[2 * 4 * 10240];   // bf16 hi/lo (node GEMM PQ)
__device__ __nv_bfloat16 g_wu[8 * 10240];        // bf16 hi/lo (update GEMM)
__device__ __half g_wm2[4 * 10240];              // fp16 hi/lo (edge GEMM2)
__device__ __half g_wp1[4 * 10240];              // fp16 hi/lo (edge GEMM3)

// ---------------- helpers ----------------
__device__ __forceinline__ void red_add_v4(float* p, float4 v) {
    asm volatile("red.global.add.v4.f32 [%0], {%1,%2,%3,%4};"
                 :: "l"(p), "f"(v.x), "f"(v.y), "f"(v.z), "f"(v.w) : "memory");
}
__device__ __forceinline__ void red_add_v2(float* p, float2 v) {
    asm volatile("red.global.add.v2.f32 [%0], {%1,%2};"
                 :: "l"(p), "f"(v.x), "f"(v.y) : "memory");
}
__device__ __forceinline__ void red_add_f64(double* p, double v) {
    asm volatile("red.global.add.f64 [%0], %1;" :: "l"(p), "d"(v) : "memory");
}
__device__ __forceinline__ unsigned pkbf(__nv_bfloat16 a, __nv_bfloat16 b) {
    return ((unsigned)__bfloat16_as_ushort(b) << 16) | (unsigned)__bfloat16_as_ushort(a);
}
__device__ __forceinline__ unsigned pkhf(__half a, __half b) {
    return ((unsigned)__half_as_ushort(b) << 16) | (unsigned)__half_as_ushort(a);
}
__device__ __forceinline__ void split1(float x, __nv_bfloat16& h, __nv_bfloat16& l) {
    h = __float2bfloat16(x);
    l = __float2bfloat16(x - __bfloat162float(h));
}
__device__ __forceinline__ void split1h(float x, __half& h, __half& l) {
    h = __float2half_rn(x);
    l = __float2half_rn(x - __half2float(h));
}
__device__ __forceinline__ void mma_bf16(float* d, const unsigned* a, unsigned b0, unsigned b1) {
    asm volatile("mma.sync.aligned.m16n8k16.row.col.f32.bf16.bf16.f32 "
                 "{%0,%1,%2,%3},{%4,%5,%6,%7},{%8,%9},{%0,%1,%2,%3};"
                 : "+f"(d[0]), "+f"(d[1]), "+f"(d[2]), "+f"(d[3])
                 : "r"(a[0]), "r"(a[1]), "r"(a[2]), "r"(a[3]), "r"(b0), "r"(b1));
}
__device__ __forceinline__ void mma_f16(float* d, const unsigned* a, unsigned b0, unsigned b1) {
    asm volatile("mma.sync.aligned.m16n8k16.row.col.f32.f16.f16.f32 "
                 "{%0,%1,%2,%3},{%4,%5,%6,%7},{%8,%9},{%0,%1,%2,%3};"
                 : "+f"(d[0]), "+f"(d[1]), "+f"(d[2]), "+f"(d[3])
                 : "r"(a[0]), "r"(a[1]), "r"(a[2]), "r"(a[3]), "r"(b0), "r"(b1));
}
__device__ __forceinline__ float4 dec4(uint2 r) {
    __half2 a = *(__half2*)&r.x, b = *(__half2*)&r.y;
    return make_float4(__low2float(a), __high2float(a), __low2float(b), __high2float(b));
}
// BN affine from raw stats (bit-identical to k_fin math)
__device__ __forceinline__ void bn_affine(const double* sum, const double* sumsq,
                                          const float* g, const float* bb,
                                          int c, int rows, float& a, float& cc) {
    double m = sum[c] / rows;
    double v = sumsq[c] / rows - m * m;
    float rstd = rsqrtf((float)v + BN_EPS);
    a = g[c] * rstd;
    cc = bb[c] - (float)m * a;
}

#define W_CHUNK 10240            // elements per W chunk (2 planes x 128 x 40)
#define W_PLANE 5120
#define A_CHUNK1 5120            // fp16 A: 1 plane x 128 x 40
#define A_CHUNK2 10240           // bf16 A: 2 planes x 128 x 40
#define A_PLANE 5120
#define STAGE_F32  (128 * 132)   // 67584 bytes as fp32
#define ETILES 3907              // ceil(EE/128)
#define NTILES 391               // ceil(NN/128)

// persistent EDGE kernel smem: [W 81920][shared: stage 67584 | A 2x10240B][red 4096][bn 1024]
#define PW_BYTES   (4 * W_CHUNK * 2)
#define P_SH_OFF   PW_BYTES
#define P_RED_OFF  (PW_BYTES + STAGE_F32 * 4)
#define P_BN_OFF   (P_RED_OFF + 4096)
#define P_SMEM     (P_BN_OFF + 1024)                   // 154624

// persistent PQ kernel smem: [W 81920][A 2x20480][stage 67584]
#define Q_A_OFF    PW_BYTES
#define Q_ST_OFF   (PW_BYTES + 2 * A_CHUNK2 * 2)
#define Q_SMEM     (Q_ST_OFF + STAGE_F32 * 4)          // 190464

// ---------------- zero scratch ----------------
__global__ void k_zero() {
    int idx = blockIdx.x * blockDim.x + threadIdx.x;
    int stride = gridDim.x * blockDim.x;
    for (int i = idx; i < NN * 128; i += stride) g_haggr[i] = 0.f;
    for (int i = idx; i < NN * 2; i += stride) g_possum[i] = 0.f;
    for (int i = idx; i < NN; i += stride) g_deg[i] = 0;
    if (idx < 5 * 128) { g_sum[idx] = 0.0; g_sumsq[idx] = 0.0; }
}

// ---------------- weight prep ----------------
__global__ void k_prepw(const float* __restrict__ Wm1, const float* __restrict__ Wm2,
                        const float* __restrict__ Wp1, const float* __restrict__ Wu1)
{
    int idx = blockIdx.x * blockDim.x + threadIdx.x;
    int stride = gridDim.x * blockDim.x;
    for (int i = idx; i < 2 * 4 * W_CHUNK; i += stride) {
        int ci = i / W_CHUNK, rem = i % W_CHUNK;
        int plane = rem / W_PLANE, r2 = rem % W_PLANE;
        int n = r2 / 40, k = r2 % 40;
        int nt = ci >> 2, kc = ci & 3, kg = kc * 32 + k;
        float v = 0.f;
        if (k < 32) v = nt ? Wm1[(128 + kg) * 128 + n] : Wm1[kg * 128 + n];
        __nv_bfloat16 h, l; split1(v, h, l);
        g_wpq[i] = plane ? l : h;
    }
    for (int i = idx; i < 4 * W_CHUNK; i += stride) {
        int ci = i / W_CHUNK, rem = i % W_CHUNK;
        int plane = rem / W_PLANE, r2 = rem % W_PLANE;
        int n = r2 / 40, k = r2 % 40;
        int kg = ci * 32 + k;
        float v2 = (k < 32) ? Wm2[kg * 128 + n] : 0.f;
        float vp = (k < 32) ? Wp1[kg * 128 + n] : 0.f;
        __half h, l;
        split1h(v2, h, l); g_wm2[i] = plane ? l : h;
        split1h(vp, h, l); g_wp1[i] = plane ? l : h;
    }
    for (int i = idx; i < 8 * W_CHUNK; i += stride) {
        int ci = i / W_CHUNK, rem = i % W_CHUNK;
        int plane = rem / W_PLANE, r2 = rem % W_PLANE;
        int n = r2 / 40, k = r2 % 40;
        int kg = ci * 32 + k;
        float v = (k < 32) ? Wu1[kg * 128 + n] : 0.f;
        __nv_bfloat16 h, l; split1(v, h, l);
        g_wu[i] = plane ? l : h;
    }
}

// ---------------- finalize BN affine (for wide-grid consumers) ----------------
__global__ void k_fin(const double* __restrict__ sum, const double* __restrict__ sumsq,
                      const float* __restrict__ g, const float* __restrict__ bb,
                      float* __restrict__ acta, float* __restrict__ actc,
                      int rows, int ncols)
{
    int c = threadIdx.x;
    if (c < ncols) {
        float a, cc;
        bn_affine(sum, sumsq, g, bb, c, rows, a, cc);
        acta[c] = a;
        actc[c] = cc;
    }
}

// ---------------- persistent PQ GEMM: bf16 3-split, fp16 out, W once ----------------
__global__ __launch_bounds__(512) void k_gemm_pq(
    const float* __restrict__ A, const __nv_bfloat16* __restrict__ Wt,
    __half* __restrict__ PQout)
{
    extern __shared__ char smem[];
    unsigned short* smW = (unsigned short*)smem;
    unsigned short* smA = (unsigned short*)(smem + Q_A_OFF);
    float* stage = (float*)(smem + Q_ST_OFF);

    const int t = threadIdx.x;
    const int w = t >> 5, l = t & 31;
    const int wm = w & 3, wn = w >> 2;
    const int lr = l >> 2, lc = 2 * (l & 3);
    const int ncolBase = blockIdx.y * 128;
    const int rl = t >> 2;
    const int cg = (t & 3) * 8;

    {
        const uint4* s4 = (const uint4*)((const char*)Wt + (size_t)blockIdx.y * 4 * W_CHUNK * 2);
        uint4* d4 = (uint4*)smW;
#pragma unroll 4
        for (int i = t; i < PW_BYTES / 16; i += 512) d4[i] = s4[i];
    }
    __syncthreads();

    for (int tile = blockIdx.x; tile < NTILES; tile += gridDim.x) {
        const int rowBase = tile * 128;
        const int grow = rowBase + rl;
        const bool avalid = grow < NN;

        float acc[2][4][4];
#pragma unroll
        for (int i = 0; i < 2; i++)
#pragma unroll
            for (int j = 0; j < 4; j++)
#pragma unroll
                for (int k = 0; k < 4; k++) acc[i][j][k] = 0.f;

        float4 pv0, pv1;
        auto loadA = [&](int kc) {
            int kg = kc * 32 + cg;
            if (avalid) {
                pv0 = *(const float4*)(A + (size_t)grow * 128 + kg);
                pv1 = *(const float4*)(A + (size_t)grow * 128 + kg + 4);
            }
        };
        auto storeA = [&](int st) {
            float vv[8] = {0.f, 0.f, 0.f, 0.f, 0.f, 0.f, 0.f, 0.f};
            if (avalid) {
                vv[0] = pv0.x; vv[1] = pv0.y; vv[2] = pv0.z; vv[3] = pv0.w;
                vv[4] = pv1.x; vv[5] = pv1.y; vv[6] = pv1.z; vv[7] = pv1.w;
            }
            unsigned ph[4], pl[4];
#pragma unroll
            for (int j = 0; j < 4; j++) {
                __nv_bfloat16 h0, l0, h1, l1;
                split1(vv[2 * j], h0, l0);
                split1(vv[2 * j + 1], h1, l1);
                ph[j] = pkbf(h0, h1);
                pl[j] = pkbf(l0, l1);
            }
            unsigned short* Ah = smA + st * A_CHUNK2;
            *(uint4*)(Ah + rl * 40 + cg) = make_uint4(ph[0], ph[1], ph[2], ph[3]);
            *(uint4*)(Ah + A_PLANE + rl * 40 + cg) = make_uint4(pl[0], pl[1], pl[2], pl[3]);
        };

        loadA(0);
        storeA(0);
        __syncthreads();

        for (int kc = 0; kc < 4; kc++) {
            if (kc + 1 < 4) loadA(kc + 1);
            const unsigned short* Ah = smA + (kc & 1) * A_CHUNK2;
            const unsigned short* Al = Ah + A_PLANE;
            const unsigned short* Bh = smW + kc * W_CHUNK;
            const unsigned short* Bl = Bh + W_PLANE;
#pragma unroll
            for (int ks = 0; ks < 2; ks++) {
                int kb = ks * 16;
                unsigned ah[2][4], al2[2][4];
#pragma unroll
                for (int mt = 0; mt < 2; mt++) {
                    int rb = wm * 32 + mt * 16 + lr;
                    ah[mt][0] = *(const unsigned*)(Ah + rb * 40 + kb + lc);
                    ah[mt][1] = *(const unsigned*)(Ah + (rb + 8) * 40 + kb + lc);
                    ah[mt][2] = *(const unsigned*)(Ah + rb * 40 + kb + lc + 8);
                    ah[mt][3] = *(const unsigned*)(Ah + (rb + 8) * 40 + kb + lc + 8);
                    al2[mt][0] = *(const unsigned*)(Al + rb * 40 + kb + lc);
                    al2[mt][1] = *(const unsigned*)(Al + (rb + 8) * 40 + kb + lc);
                    al2[mt][2] = *(const unsigned*)(Al + rb * 40 + kb + lc + 8);
                    al2[mt][3] = *(const unsigned*)(Al + (rb + 8) * 40 + kb + lc + 8);
                }
#pragma unroll
                for (int nt = 0; nt < 4; nt++) {
                    int nb = wn * 32 + nt * 8 + lr;
                    unsigned bh0 = *(const unsigned*)(Bh + nb * 40 + kb + lc);
                    unsigned bh1 = *(const unsigned*)(Bh + nb * 40 + kb + lc + 8);
                    unsigned bl0 = *(const unsigned*)(Bl + nb * 40 + kb + lc);
                    unsigned bl1 = *(const unsigned*)(Bl + nb * 40 + kb + lc + 8);
#pragma unroll
                    for (int mt = 0; mt < 2; mt++) {
                        mma_bf16(acc[mt][nt], ah[mt], bh0, bh1);
                        mma_bf16(acc[mt][nt], ah[mt], bl0, bl1);
                        mma_bf16(acc[mt][nt], al2[mt], bh0, bh1);
                    }
                }
            }
            if (kc + 1 < 4) {
                storeA((kc + 1) & 1);
                __syncthreads();
            }
        }

#pragma unroll
        for (int mt = 0; mt < 2; mt++) {
#pragma unroll
            for (int nt = 0; nt < 4; nt++) {
                int row = wm * 32 + mt * 16 + lr;
                int col = wn * 32 + nt * 8 + lc;
                stage[row * 132 + col]           = acc[mt][nt][0];
                stage[row * 132 + col + 1]       = acc[mt][nt][1];
                stage[(row + 8) * 132 + col]     = acc[mt][nt][2];
                stage[(row + 8) * 132 + col + 1] = acc[mt][nt][3];
            }
        }
        __syncthreads();

        for (int i = t; i < 128 * 32; i += 512) {
            int row = i >> 5;
            int colq = (i & 31) * 4;
            int rowg = rowBase + row;
            if (rowg < NN) {
                float4 v = *(float4*)(stage + row * 132 + colq);
                uint2 o = make_uint2(pkhf(__float2half_rn(v.x), __float2half_rn(v.y)),
                                     pkhf(__float2half_rn(v.z), __float2half_rn(v.w)));
                *(uint2*)(PQout + (size_t)rowg * 256 + ncolBase + colq) = o;
            }
        }
        __syncthreads();
    }
}

// ---------------- node GEMM (update MLP): bf16 3-split, fp32 out ----------------
__global__ __launch_bounds__(512) void k_gemm_u(
    const float* __restrict__ A, const float* __restrict__ A2,
    const __nv_bfloat16* __restrict__ Wt, const float* __restrict__ bias,
    float* __restrict__ Cf,
    double* __restrict__ sumOut, double* __restrict__ sumsqOut)
{
    extern __shared__ char smem[];
    unsigned short* smW = (unsigned short*)smem;
    unsigned short* smA = smW + 8 * W_CHUNK;

    const int t = threadIdx.x;
    const int w = t >> 5, l = t & 31;
    const int wm = w & 3, wn = w >> 2;
    const int lr = l >> 2, lc = 2 * (l & 3);
    const int rowBase = blockIdx.x * 128;

    {
        const uint4* s4 = (const uint4*)Wt;
        uint4* d4 = (uint4*)smW;
        const int tot = 8 * W_CHUNK * 2 / 16;
#pragma unroll 4
        for (int i = t; i < tot; i += 512) d4[i] = s4[i];
    }

    const int rl = t >> 2;
    const int cg = (t & 3) * 8;
    const int grow = rowBase + rl;
    const bool avalid = grow < NN;

    float acc[2][4][4];
#pragma unroll
    for (int i = 0; i < 2; i++)
#pragma unroll
        for (int j = 0; j < 4; j++)
#pragma unroll
            for (int k = 0; k < 4; k++) acc[i][j][k] = 0.f;

    float4 pv0, pv1;
    auto loadA = [&](int kc) {
        int kg = kc * 32 + cg;
        if (avalid) {
            const float* As = (kg < 128) ? A : A2;
            int k2 = kg & 127;
            pv0 = *(const float4*)(As + (size_t)grow * 128 + k2);
            pv1 = *(const float4*)(As + (size_t)grow * 128 + k2 + 4);
        }
    };
    auto storeA = [&](int st) {
        float vv[8] = {0.f, 0.f, 0.f, 0.f, 0.f, 0.f, 0.f, 0.f};
        if (avalid) {
            vv[0] = pv0.x; vv[1] = pv0.y; vv[2] = pv0.z; vv[3] = pv0.w;
            vv[4] = pv1.x; vv[5] = pv1.y; vv[6] = pv1.z; vv[7] = pv1.w;
        }
        unsigned ph[4], pl[4];
#pragma unroll
        for (int j = 0; j < 4; j++) {
            __nv_bfloat16 h0, l0, h1, l1;
            split1(vv[2 * j], h0, l0);
            split1(vv[2 * j + 1], h1, l1);
            ph[j] = pkbf(h0, h1);
            pl[j] = pkbf(l0, l1);
        }
        unsigned short* Ah = smA + st * A_CHUNK2;
        *(uint4*)(Ah + rl * 40 + cg) = make_uint4(ph[0], ph[1], ph[2], ph[3]);
        *(uint4*)(Ah + A_PLANE + rl * 40 + cg) = make_uint4(pl[0], pl[1], pl[2], pl[3]);
    };

    loadA(0);
    storeA(0);
    __syncthreads();

    for (int kc = 0; kc < 8; kc++) {
        if (kc + 1 < 8) loadA(kc + 1);
        const unsigned short* Ah = smA + (kc & 1) * A_CHUNK2;
        const unsigned short* Al = Ah + A_PLANE;
        const unsigned short* Bh = smW + kc * W_CHUNK;
        const unsigned short* Bl = Bh + W_PLANE;
#pragma unroll
        for (int ks = 0; ks < 2; ks++) {
            int kb = ks * 16;
            unsigned ah[2][4], al2[2][4];
#pragma unroll
            for (int mt = 0; mt < 2; mt++) {
                int rb = wm * 32 + mt * 16 + lr;
                ah[mt][0] = *(const unsigned*)(Ah + rb * 40 + kb + lc);
                ah[mt][1] = *(const unsigned*)(Ah + (rb + 8) * 40 + kb + lc);
                ah[mt][2] = *(const unsigned*)(Ah + rb * 40 + kb + lc + 8);
                ah[mt][3] = *(const unsigned*)(Ah + (rb + 8) * 40 + kb + lc + 8);
                al2[mt][0] = *(const unsigned*)(Al + rb * 40 + kb + lc);
                al2[mt][1] = *(const unsigned*)(Al + (rb + 8) * 40 + kb + lc);
                al2[mt][2] = *(const unsigned*)(Al + rb * 40 + kb + lc + 8);
                al2[mt][3] = *(const unsigned*)(Al + (rb + 8) * 40 + kb + lc + 8);
            }
#pragma unroll
            for (int nt = 0; nt < 4; nt++) {
                int nb = wn * 32 + nt * 8 + lr;
                unsigned bh0 = *(const unsigned*)(Bh + nb * 40 + kb + lc);
                unsigned bh1 = *(const unsigned*)(Bh + nb * 40 + kb + lc + 8);
                unsigned bl0 = *(const unsigned*)(Bl + nb * 40 + kb + lc);
                unsigned bl1 = *(const unsigned*)(Bl + nb * 40 + kb + lc + 8);
#pragma unroll
                for (int mt = 0; mt < 2; mt++) {
                    mma_bf16(acc[mt][nt], ah[mt], bh0, bh1);
                    mma_bf16(acc[mt][nt], ah[mt], bl0, bl1);
                    mma_bf16(acc[mt][nt], al2[mt], bh0, bh1);
                }
            }
        }
        if (kc + 1 < 8) {
            storeA((kc + 1) & 1);
            __syncthreads();
        }
    }
    __syncthreads();

    float* stage = (float*)smem;
#pragma unroll
    for (int mt = 0; mt < 2; mt++) {
#pragma unroll
        for (int nt = 0; nt < 4; nt++) {
            int row = wm * 32 + mt * 16 + lr;
            int col = wn * 32 + nt * 8 + lc;
            float b0 = __ldg(bias + col);
            float b1 = __ldg(bias + col + 1);
            bool v0 = (rowBase + row) < NN;
            bool v1 = (rowBase + row + 8) < NN;
            stage[row * 132 + col]       = v0 ? acc[mt][nt][0] + b0 : 0.f;
            stage[row * 132 + col + 1]   = v0 ? acc[mt][nt][1] + b1 : 0.f;
            stage[(row + 8) * 132 + col]     = v1 ? acc[mt][nt][2] + b0 : 0.f;
            stage[(row + 8) * 132 + col + 1] = v1 ? acc[mt][nt][3] + b1 : 0.f;
        }
    }
    __syncthreads();

    float* sb = (float*)(smem + STAGE_F32 * 4);
    float* qb = sb + 512;
    {
        int c = t & 127, qq = t >> 7;
        float s = 0.f, q = 0.f;
#pragma unroll 8
        for (int r = 0; r < 32; r++) {
            float v = stage[(qq * 32 + r) * 132 + c];
            s += v; q += v * v;
        }
        sb[qq * 128 + c] = s;
        qb[qq * 128 + c] = q;
    }

    for (int i = t; i < 128 * 32; i += 512) {
        int row = i >> 5;
        int colq = (i & 31) * 4;
        int rowg = rowBase + row;
        if (rowg < NN) {
            float4 v = *(float4*)(stage + row * 132 + colq);
            *(float4*)(Cf + (size_t)rowg * 128 + colq) = v;
        }
    }

    __syncthreads();
    if (t < 128) {
        float s = sb[t] + sb[128 + t] + sb[256 + t] + sb[384 + t];
        float q = qb[t] + qb[128 + t] + qb[256 + t] + qb[384 + t];
        red_add_f64(&sumOut[t], (double)s);
        red_add_f64(&sumsqOut[t], (double)q);
    }
}

// ---------------- persistent edge GEMM: fp16, W once, inline BN-affine preamble ----------------
// AMODE 2: assemble from fp16 g_PQ (GEMM2);  AMODE 3: fp16 A rows (GEMM3)
template<int AMODE, bool AGGR>
__global__ __launch_bounds__(512) void k_gemm_p(
    const __half* __restrict__ Ain,
    const __half* __restrict__ Wt,
    const float* __restrict__ bias,
    const double* __restrict__ sumIn, const double* __restrict__ sumsqIn,
    const float* __restrict__ gammaIn, const float* __restrict__ betaIn,
    __half* __restrict__ Ch,
    const int* __restrict__ srcIdx, const int* __restrict__ dstIdx,
    const float* __restrict__ dist,
    const float* __restrict__ wlast, const float* __restrict__ bm1v,
    double* __restrict__ sumOut, double* __restrict__ sumsqOut,
    float* __restrict__ aggrOut)
{
    extern __shared__ char smem[];
    unsigned short* smW = (unsigned short*)smem;
    unsigned short* smA = (unsigned short*)(smem + P_SH_OFF);
    float* stage = (float*)(smem + P_SH_OFF);
    float* sb = (float*)(smem + P_RED_OFF);
    float* qb = sb + 512;
    float* bna = (float*)(smem + P_BN_OFF);
    float* bnc = bna + 128;

    const int t = threadIdx.x;
    const int w = t >> 5, l = t & 31;
    const int wm = w & 3, wn = w >> 2;
    const int lr = l >> 2, lc = 2 * (l & 3);
    const int rl = t >> 2;
    const int cg = (t & 3) * 8;

    // inline BN affine (148 blocks only — negligible FP64 cost; replaces a k_fin launch)
    if (t < 128) {
        float a, c;
        bn_affine(sumIn, sumsqIn, gammaIn, betaIn, t, EE, a, c);
        bna[t] = a;
        bnc[t] = c;
    }
    {
        const uint4* s4 = (const uint4*)Wt;
        uint4* d4 = (uint4*)smW;
#pragma unroll 4
        for (int i = t; i < PW_BYTES / 16; i += 512) d4[i] = s4[i];
    }
    __syncthreads();

    for (int tile = blockIdx.x; tile < ETILES; tile += gridDim.x) {
        const int rowBase = tile * 128;
        const int grow = rowBase + rl;
        const bool avalid = grow < EE;
        int ed = 0, es = 0;
        float de = 0.f;
        if (avalid) {
            if (AMODE == 2 || AGGR) ed = dstIdx[grow];
            if (AMODE == 2) { es = srcIdx[grow]; de = dist[grow]; }
        }

        float acc[2][4][4];
#pragma unroll
        for (int i = 0; i < 2; i++)
#pragma unroll
            for (int j = 0; j < 4; j++)
#pragma unroll
                for (int k = 0; k < 4; k++) acc[i][j][k] = 0.f;

        float4 pv0, pv1, pv2, pv3;

        auto loadA = [&](int kc) {
            int kg = kc * 32 + cg;
            if (avalid) {
                if (AMODE == 3) {
                    uint4 r = *(const uint4*)(Ain + (size_t)grow * 128 + kg);
                    pv0 = dec4(make_uint2(r.x, r.y));
                    pv1 = dec4(make_uint2(r.z, r.w));
                } else {
                    uint4 rp = *(const uint4*)(g_PQ + (size_t)ed * 256 + kg);
                    uint4 rq = *(const uint4*)(g_PQ + (size_t)es * 256 + 128 + kg);
                    pv0 = dec4(make_uint2(rp.x, rp.y));
                    pv1 = dec4(make_uint2(rp.z, rp.w));
                    pv2 = dec4(make_uint2(rq.x, rq.y));
                    pv3 = dec4(make_uint2(rq.z, rq.w));
                }
            }
        };
        auto storeA = [&](int kc, int st) {
            int kg = kc * 32 + cg;
            float vv[8] = {0.f, 0.f, 0.f, 0.f, 0.f, 0.f, 0.f, 0.f};
            if (avalid) {
                vv[0] = pv0.x; vv[1] = pv0.y; vv[2] = pv0.z; vv[3] = pv0.w;
                vv[4] = pv1.x; vv[5] = pv1.y; vv[6] = pv1.z; vv[7] = pv1.w;
                if (AMODE == 2) {
                    float q4[8] = {pv2.x, pv2.y, pv2.z, pv2.w, pv3.x, pv3.y, pv3.z, pv3.w};
#pragma unroll
                    for (int j = 0; j < 8; j++) {
                        float wl = __ldg(wlast + kg + j);
                        float bb = __ldg(bm1v + kg + j);
                        vv[j] = vv[j] + q4[j] + de * wl + bb;
                    }
                }
                float4 a0 = *(const float4*)(bna + kg);
                float4 a1 = *(const float4*)(bna + kg + 4);
                float4 c0 = *(const float4*)(bnc + kg);
                float4 c1 = *(const float4*)(bnc + kg + 4);
                vv[0] = fmaxf(fmaf(vv[0], a0.x, c0.x), 0.f);
                vv[1] = fmaxf(fmaf(vv[1], a0.y, c0.y), 0.f);
                vv[2] = fmaxf(fmaf(vv[2], a0.z, c0.z), 0.f);
                vv[3] = fmaxf(fmaf(vv[3], a0.w, c0.w), 0.f);
                vv[4] = fmaxf(fmaf(vv[4], a1.x, c1.x), 0.f);
                vv[5] = fmaxf(fmaf(vv[5], a1.y, c1.y), 0.f);
                vv[6] = fmaxf(fmaf(vv[6], a1.z, c1.z), 0.f);
                vv[7] = fmaxf(fmaf(vv[7], a1.w, c1.w), 0.f);
                if (AGGR) {
                    red_add_v4(aggrOut + (size_t)ed * 128 + kg,
                               make_float4(vv[0], vv[1], vv[2], vv[3]));
                    red_add_v4(aggrOut + (size_t)ed * 128 + kg + 4,
                               make_float4(vv[4], vv[5], vv[6], vv[7]));
                }
            }
            unsigned ph[4];
#pragma unroll
            for (int j = 0; j < 4; j++)
                ph[j] = pkhf(__float2half_rn(vv[2 * j]), __float2half_rn(vv[2 * j + 1]));
            unsigned short* Ah = smA + st * A_CHUNK1;
            *(uint4*)(Ah + rl * 40 + cg) = make_uint4(ph[0], ph[1], ph[2], ph[3]);
        };

        loadA(0);
        storeA(0, 0);
        __syncthreads();

        for (int kc = 0; kc < 4; kc++) {
            if (kc + 1 < 4) loadA(kc + 1);
            const unsigned short* Ah = smA + (kc & 1) * A_CHUNK1;
            const unsigned short* Bh = smW + kc * W_CHUNK;
            const unsigned short* Bl = Bh + W_PLANE;
#pragma unroll
            for (int ks = 0; ks < 2; ks++) {
                int kb = ks * 16;
                unsigned ah[2][4];
#pragma unroll
                for (int mt = 0; mt < 2; mt++) {
                    int rb = wm * 32 + mt * 16 + lr;
                    ah[mt][0] = *(const unsigned*)(Ah + rb * 40 + kb + lc);
                    ah[mt][1] = *(const unsigned*)(Ah + (rb + 8) * 40 + kb + lc);
                    ah[mt][2] = *(const unsigned*)(Ah + rb * 40 + kb + lc + 8);
                    ah[mt][3] = *(const unsigned*)(Ah + (rb + 8) * 40 + kb + lc + 8);
                }
#pragma unroll
                for (int nt = 0; nt < 4; nt++) {
                    int nb = wn * 32 + nt * 8 + lr;
                    unsigned bh0 = *(const unsigned*)(Bh + nb * 40 + kb + lc);
                    unsigned bh1 = *(const unsigned*)(Bh + nb * 40 + kb + lc + 8);
                    unsigned bl0 = *(const unsigned*)(Bl + nb * 40 + kb + lc);
                    unsigned bl1 = *(const unsigned*)(Bl + nb * 40 + kb + lc + 8);
#pragma unroll
                    for (int mt = 0; mt < 2; mt++) {
                        mma_f16(acc[mt][nt], ah[mt], bh0, bh1);
                        mma_f16(acc[mt][nt], ah[mt], bl0, bl1);
                    }
                }
            }
            if (kc + 1 < 4) {
                storeA(kc + 1, (kc + 1) & 1);
                __syncthreads();
            }
        }
        __syncthreads();   // A-buffer reads done; stage may overwrite region

#pragma unroll
        for (int mt = 0; mt < 2; mt++) {
#pragma unroll
            for (int nt = 0; nt < 4; nt++) {
                int row = wm * 32 + mt * 16 + lr;
                int col = wn * 32 + nt * 8 + lc;
                float b0 = __ldg(bias + col);
                float b1 = __ldg(bias + col + 1);
                bool v0 = (rowBase + row) < EE;
                bool v1 = (rowBase + row + 8) < EE;
                stage[row * 132 + col]       = v0 ? acc[mt][nt][0] + b0 : 0.f;
                stage[row * 132 + col + 1]   = v0 ? acc[mt][nt][1] + b1 : 0.f;
                stage[(row + 8) * 132 + col]     = v1 ? acc[mt][nt][2] + b0 : 0.f;
                stage[(row + 8) * 132 + col + 1] = v1 ? acc[mt][nt][3] + b1 : 0.f;
            }
        }
        __syncthreads();

        {
            int c = t & 127, qq = t >> 7;
            float s = 0.f, q = 0.f;
#pragma unroll 8
            for (int r = 0; r < 32; r++) {
                float v = stage[(qq * 32 + r) * 132 + c];
                s += v; q += v * v;
            }
            sb[qq * 128 + c] = s;
            qb[qq * 128 + c] = q;
        }

        for (int i = t; i < 128 * 32; i += 512) {
            int row = i >> 5;
            int colq = (i & 31) * 4;
            int rowg = rowBase + row;
            if (rowg < EE) {
                float4 v = *(float4*)(stage + row * 132 + colq);
                uint2 o = make_uint2(pkhf(__float2half_rn(v.x), __float2half_rn(v.y)),
                                     pkhf(__float2half_rn(v.z), __float2half_rn(v.w)));
                *(uint2*)(Ch + (size_t)rowg * 128 + colq) = o;
            }
        }
        __syncthreads();   // stage reads done before next tile's storeA

        if (t < 128) {
            float s = sb[t] + sb[128 + t] + sb[256 + t] + sb[384 + t];
            float q = qb[t] + qb[128 + t] + qb[256 + t] + qb[384 + t];
            red_add_f64(&sumOut[t], (double)s);
            red_add_f64(&sumsqOut[t], (double)q);
        }
    }
}

// ---------------- edge stats (BN1), fp16 PQ, 2-way unrolled + deg histogram ----------------
__global__ __launch_bounds__(256) void k_edgestats(
    const int* __restrict__ src, const int* __restrict__ dst,
    const float* __restrict__ pos,
    const float* __restrict__ wlast, const float* __restrict__ bm1,
    double* __restrict__ sum, double* __restrict__ sumsq)
{
    int lane = threadIdx.x & 31;
    int wg = (blockIdx.x * blockDim.x + threadIdx.x) >> 5;
    int nw = (gridDim.x * blockDim.x) >> 5;
    int c = lane * 4;
    float4 wl = *(const float4*)(wlast + c);
    float4 bb = *(const float4*)(bm1 + c);
    float4 s = make_float4(0.f, 0.f, 0.f, 0.f);
    float4 q = make_float4(0.f, 0.f, 0.f, 0.f);
    int nw2 = nw * 2;
    for (int e = wg; e < EE; e += nw2) {
        int eB = e + nw;
        bool hasB = eB < EE;
        int sjA = src[e], djA = dst[e];
        int sjB = hasB ? src[eB] : 0, djB = hasB ? dst[eB] : 0;
        float2 psA = ((const float2*)pos)[sjA];
        float2 pdA = ((const float2*)pos)[djA];
        float2 psB = ((const float2*)pos)[sjB];
        float2 pdB = ((const float2*)pos)[djB];
        float4 pA = dec4(*(const uint2*)(g_PQ + (size_t)djA * 256 + c));
        float4 qA = dec4(*(const uint2*)(g_PQ + (size_t)sjA * 256 + 128 + c));
        float4 pB = dec4(*(const uint2*)(g_PQ + (size_t)djB * 256 + c));
        float4 qB = dec4(*(const uint2*)(g_PQ + (size_t)sjB * 256 + 128 + c));

        float dxA = psA.x - pdA.x, dyA = psA.y - pdA.y;
        float dA = sqrtf(dxA * dxA + dyA * dyA);
        float dxB = psB.x - pdB.x, dyB = psB.y - pdB.y;
        float dB = sqrtf(dxB * dxB + dyB * dyB);
        if (lane == 0) {
            ((float2*)g_diff)[e] = make_float2(dxA, dyA);
            g_dist[e] = dA;
            atomicAdd(&g_deg[djA], 1);
            if (hasB) {
                ((float2*)g_diff)[eB] = make_float2(dxB, dyB);
                g_dist[eB] = dB;
                atomicAdd(&g_deg[djB], 1);
            }
        }
        float4 x;
        x.x = pA.x + qA.x + dA * wl.x + bb.x;
        x.y = pA.y + qA.y + dA * wl.y + bb.y;
        x.z = pA.z + qA.z + dA * wl.z + bb.z;
        x.w = pA.w + qA.w + dA * wl.w + bb.w;
        s.x += x.x; s.y += x.y; s.z += x.z; s.w += x.w;
        q.x += x.x * x.x; q.y += x.y * x.y; q.z += x.z * x.z; q.w += x.w * x.w;
        if (hasB) {
            float4 y;
            y.x = pB.x + qB.x + dB * wl.x + bb.x;
            y.y = pB.y + qB.y + dB * wl.y + bb.y;
            y.z = pB.z + qB.z + dB * wl.z + bb.z;
            y.w = pB.w + qB.w + dB * wl.w + bb.w;
            s.x += y.x; s.y += y.y; s.z += y.z; s.w += y.w;
            q.x += y.x * y.x; q.y += y.y * y.y; q.z += y.z * y.z; q.w += y.w * y.w;
        }
    }
    __shared__ float sb[8][128], qb[8][128];
    int wi = threadIdx.x >> 5;
    *(float4*)&sb[wi][c] = s;
    *(float4*)&qb[wi][c] = q;
    __syncthreads();
    if (threadIdx.x < 128) {
        float ts = 0.f, tq = 0.f;
#pragma unroll
        for (int i = 0; i < 8; i++) { ts += sb[i][threadIdx.x]; tq += qb[i][threadIdx.x]; }
        red_add_f64(&sum[threadIdx.x], (double)ts);
        red_add_f64(&sumsq[threadIdx.x], (double)tq);
    }
}

// ---------------- gemv over fp16 S (precomputed BN3 affine) + fused BN4 stats ----------------
__global__ void k_gemv(const __half* __restrict__ S, const float* __restrict__ Wp2,
                       const float* __restrict__ bp2,
                       const float* __restrict__ acta, const float* __restrict__ actc,
                       float* __restrict__ out,
                       double* __restrict__ sum, double* __restrict__ sumsq)
{
    int e = (blockIdx.x * blockDim.x + threadIdx.x) >> 5;
    int lane = threadIdx.x & 31;
    int wi = threadIdx.x >> 5;
    __shared__ float ssb[8], qqb[8];
    float myval = 0.f;
    if (e < EE) {
        int c = lane * 4;
        float4 v = dec4(*(const uint2*)(S + (size_t)e * 128 + c));
        float4 wv = *(const float4*)(Wp2 + c);
        float d = fmaxf(fmaf(v.x, acta[c + 0], actc[c + 0]), 0.f) * wv.x
                + fmaxf(fmaf(v.y, acta[c + 1], actc[c + 1]), 0.f) * wv.y
                + fmaxf(fmaf(v.z, acta[c + 2], actc[c + 2]), 0.f) * wv.z
                + fmaxf(fmaf(v.w, acta[c + 3], actc[c + 3]), 0.f) * wv.w;
#pragma unroll
        for (int o = 16; o > 0; o >>= 1) d += __shfl_down_sync(0xffffffffu, d, o);
        if (lane == 0) {
            myval = d + bp2[0];
            out[e] = myval;
        }
    }
    if (lane == 0) { ssb[wi] = myval; qqb[wi] = myval * myval; }
    __syncthreads();
    if (threadIdx.x == 0) {
        float s = 0.f, q = 0.f;
#pragma unroll
        for (int i = 0; i < 8; i++) { s += ssb[i]; q += qqb[i]; }
        red_add_f64(sum, (double)s);
        red_add_f64(sumsq, (double)q);
    }
}

// ---------------- pos aggregation (precomputed BN4 affine) ----------------
__global__ void k_posaggr(const int* __restrict__ dst,
                          const float* __restrict__ a4, const float* __restrict__ c4)
{
    int e = blockIdx.x * blockDim.x + threadIdx.x;
    if (e >= EE) return;
    float sc = fmaxf(fmaf(g_sp[e], a4[0], c4[0]), 0.f);
    float2 df = ((const float2*)g_diff)[e];
    int d = dst[e];
    red_add_v2(g_possum + 2 * (size_t)d, make_float2(df.x * sc, df.y * sc));
}

// ---------------- final residual write (precomputed BN5 affine) ----------------
__global__ void k_final(const float* __restrict__ h, const float* __restrict__ pos,
                        const float* __restrict__ a5, const float* __restrict__ c5,
                        float* __restrict__ out)
{
    int i = blockIdx.x * blockDim.x + threadIdx.x;
    if (i < NN * 128) {
        int c = i & 127;
        float u = g_U[i];
        out[i] = h[i] + fmaxf(fmaf(u, a5[c], c5[c]), 0.f);
    }
    if (i < NN) {
        float cnt = fmaxf((float)g_deg[i], 1.f);
        out[NN * 128 + 2 * i + 0] = pos[2 * i + 0] + g_possum[2 * i + 0] / cnt;
        out[NN * 128 + 2 * i + 1] = pos[2 * i + 1] + g_possum[2 * i + 1] / cnt;
    }
}

extern "C" void kernel_launch(void* const* d_in, const int* in_sizes, int n_in,
                              void* d_out, int out_size)
{
    const float* h    = (const float*)d_in[0];
    const float* pos  = (const float*)d_in[1];
    const int*   ei   = (const int*)d_in[3];
    const int*   src  = ei;
    const int*   dst  = ei + EE;
    const float* Wm1  = (const float*)d_in[4];
    const float* bm1  = (const float*)d_in[5];
    const float* gm1  = (const float*)d_in[6];
    const float* bbm1 = (const float*)d_in[7];
    const float* Wm2  = (const float*)d_in[8];
    const float* bm2  = (const float*)d_in[9];
    const float* gm2  = (const float*)d_in[10];
    const float* bbm2 = (const float*)d_in[11];
    const float* Wp1  = (const float*)d_in[12];
    const float* bp1  = (const float*)d_in[13];
    const float* gp1  = (const float*)d_in[14];
    const float* bbp1 = (const float*)d_in[15];
    const float* Wp2  = (const float*)d_in[16];
    const float* bp2  = (const float*)d_in[17];
    const float* gp2  = (const float*)d_in[18];
    const float* bbp2 = (const float*)d_in[19];
    const float* Wu1  = (const float*)d_in[20];
    const float* bu1  = (const float*)d_in[21];
    const float* gu1  = (const float*)d_in[22];
    const float* bbu1 = (const float*)d_in[23];
    float* out = (float*)d_out;

    void* p;
    cudaGetSymbolAddress(&p, g_PQ);   __half* PQ  = (__half*)p;
    cudaGetSymbolAddress(&p, g_X2);   __half* X2  = (__half*)p;
    cudaGetSymbolAddress(&p, g_S);    __half* S   = (__half*)p;
    cudaGetSymbolAddress(&p, g_dist); float* DIST = (float*)p;
    cudaGetSymbolAddress(&p, g_sp);   float* SP   = (float*)p;
    cudaGetSymbolAddress(&p, g_haggr); float* HAGG = (float*)p;
    cudaGetSymbolAddress(&p, g_U);    float* U    = (float*)p;
    cudaGetSymbolAddress(&p, g_sum);  double* SUM = (double*)p;
    cudaGetSymbolAddress(&p, g_sumsq); double* SSQ = (double*)p;
    cudaGetSymbolAddress(&p, g_acta); float* ACTA = (float*)p;
    cudaGetSymbolAddress(&p, g_actc); float* ACTC = (float*)p;
    cudaGetSymbolAddress(&p, g_wpq);  __nv_bfloat16* WPQ = (__nv_bfloat16*)p;
    cudaGetSymbolAddress(&p, g_wm2);  __half* WM2 = (__half*)p;
    cudaGetSymbolAddress(&p, g_wp1);  __half* WP1 = (__half*)p;
    cudaGetSymbolAddress(&p, g_wu);   __nv_bfloat16* WU  = (__nv_bfloat16*)p;

    int nsm = 148;
    cudaDeviceGetAttribute(&nsm, cudaDevAttrMultiProcessorCount, 0);

    const float* wlast = Wm1 + 256 * 128;
    const int SM8B = 8 * 20480 + 2 * 20480;  // 204800 (update GEMM)

    cudaFuncSetAttribute((const void*)k_gemm_pq,
                         cudaFuncAttributeMaxDynamicSharedMemorySize, Q_SMEM);
    cudaFuncSetAttribute((const void*)k_gemm_u,
                         cudaFuncAttributeMaxDynamicSharedMemorySize, SM8B);
    cudaFuncSetAttribute((const void*)k_gemm_p<2, false>,
                         cudaFuncAttributeMaxDynamicSharedMemorySize, P_SMEM);
    cudaFuncSetAttribute((const void*)k_gemm_p<3, true>,
                         cudaFuncAttributeMaxDynamicSharedMemorySize, P_SMEM);

    k_zero<<<2048, 256>>>();
    k_prepw<<<256, 256>>>(Wm1, Wm2, Wp1, Wu1);

    // PQ(fp16) = h @ [Wm1_top | Wm1_mid]  (persistent, bf16 3-split)
    k_gemm_pq<<<dim3(nsm, 2), 512, Q_SMEM>>>(h, WPQ, PQ);

    // BN1 stats + diff/dist/deg (fp16 PQ gather)
    k_edgestats<<<1184, 256>>>(src, dst, pos, wlast, bm1, SUM + 0, SSQ + 0);

    // GEMM2 (persistent, inline BN1 affine): X2(fp16) = bn_relu1(assemble) @ Wm2 + bm2
    k_gemm_p<2, false><<<nsm, 512, P_SMEM>>>(
        nullptr, WM2, bm2, SUM + 0, SSQ + 0, gm1, bbm1, X2,
        src, dst, DIST, wlast, bm1, SUM + 128, SSQ + 128, nullptr);

    // GEMM3 (persistent, inline BN2 affine): S(fp16) = bn_relu2(X2) @ Wp1 + bp1 + h-aggr
    k_gemm_p<3, true><<<nsm, 512, P_SMEM>>>(
        X2, WP1, bp1, SUM + 128, SSQ + 128, gm2, bbm2, S,
        nullptr, dst, nullptr, nullptr, nullptr, SUM + 256, SSQ + 256, HAGG);

    // BN3 affine (once), then pos layer 2 + fused BN4 stats
    k_fin<<<1, 128>>>(SUM + 256, SSQ + 256, gp1, bbp1, ACTA + 256, ACTC + 256, EE, 128);
    k_gemv<<<EE / 8, 256>>>(S, Wp2, bp2, ACTA + 256, ACTC + 256, SP,
                            SUM + 384, SSQ + 384);

    // BN4 affine (once), then pos aggregation
    k_fin<<<1, 128>>>(SUM + 384, SSQ + 384, gp2, bbp2, ACTA + 384, ACTC + 384, EE, 1);
    k_posaggr<<<(EE + 255) / 256, 256>>>(dst, ACTA + 384, ACTC + 384);

    // update MLP (bf16 3-split, fused BN5 stats)
    k_gemm_u<<<NTILES, 512, SM8B>>>(h, HAGG, WU, bu1, U, SUM + 512, SSQ + 512);

    // BN5 affine (once), then residual outputs
    k_fin<<<1, 128>>>(SUM + 512, SSQ + 512, gu1, bbu1, ACTA + 512, ACTC + 512, NN, 128);
    k_final<<<(NN * 128 + 255) / 256, 256>>>(h, pos, ACTA + 512, ACTC + 512, out);
}